// round 3
// baseline (speedup 1.0000x reference)
#include <cuda_runtime.h>
#include <cstdint>

#define BATCH 1024
#define SEQL  200
#define DIM   128

// Scratch (allocation-free rule: __device__ globals)
__device__ float g_buf[BATCH * DIM];
__device__ float ag_buf[BATCH * DIM];

// ---------------------------------------------------------------------------
// Packed fp32x2 FMA (Blackwell FFMA2 — only reachable via PTX fma.rn.f32x2)
// ---------------------------------------------------------------------------
__device__ __forceinline__ void ffma2(unsigned long long& d,
                                      unsigned long long a,
                                      unsigned long long b) {
    asm("fma.rn.f32x2 %0, %1, %2, %0;" : "+l"(d) : "l"(a), "l"(b));
}
__device__ __forceinline__ float2 unpack2(unsigned long long v) {
    float2 f;
    asm("mov.b64 {%0, %1}, %2;" : "=f"(f.x), "=f"(f.y) : "l"(v));
    return f;
}

// ---------------------------------------------------------------------------
// Kernel 1: g[b] = sum_l item_embedding[items[b,l]]   (HBM BW bound)
// ---------------------------------------------------------------------------
__global__ void __launch_bounds__(DIM) gather_sum_kernel(
    const float* __restrict__ emb,
    const void* __restrict__ items_raw)
{
    const int b = blockIdx.x;
    const int t = threadIdx.x;

    __shared__ int sidx[SEQL];
    __shared__ int mode64;

    if (t == 0) {
        // int64 storage => odd int32 words of first 16 elements are all zero
        const int* p = (const int*)items_raw;
        int ok = 1;
        #pragma unroll
        for (int i = 0; i < 16; i++) ok &= (p[2 * i + 1] == 0);
        mode64 = ok;
    }
    __syncthreads();

    if (mode64) {
        const long long* it = (const long long*)items_raw;
        for (int l = t; l < SEQL; l += DIM) sidx[l] = (int)it[(long long)b * SEQL + l];
    } else {
        const int* it = (const int*)items_raw;
        for (int l = t; l < SEQL; l += DIM) sidx[l] = it[b * SEQL + l];
    }
    __syncthreads();

    // 8 independent accumulator chains -> MLP 8
    float a[8];
    #pragma unroll
    for (int j = 0; j < 8; j++) a[j] = 0.f;

    #pragma unroll 1
    for (int l = 0; l < SEQL; l += 8) {
        #pragma unroll
        for (int j = 0; j < 8; j++)
            a[j] += emb[(size_t)sidx[l + j] * DIM + t];
    }
    float s = ((a[0] + a[1]) + (a[2] + a[3])) + ((a[4] + a[5]) + (a[6] + a[7]));
    g_buf[b * DIM + t] = s;
}

// ---------------------------------------------------------------------------
// Kernel 2: Y[1024,128] = Am[1024,1024] @ X[1024,128]   (+optional fused
//           selu+row-normalize epilogue writing the final output)
//
// grid = 128 blocks (8 rows each), block = (64, 2) = 128 threads.
//  - threadIdx.x = column PAIR (cols 2x, 2x+1), packed f32x2 math (FFMA2)
//  - threadIdx.y = K half (each half: K=512 in 32 chunks of 16)
// A staged in smem as DUPLICATED pairs {a,a} -> LDS.128 feeds 2 FFMA2.
// Each half stages its OWN A slice with its own 64 threads (2 elems each).
// Double-buffered smem + register prefetch hides LDG latency.
// ---------------------------------------------------------------------------
template <bool EPI>
__global__ void __launch_bounds__(128) gemm_1024x128_kernel(
    const float* __restrict__ Am,
    const float* __restrict__ X,
    float* __restrict__ Y)
{
    const int x  = threadIdx.x;            // 0..63 column pair
    const int h  = threadIdx.y;            // 0..1  K half
    const int bm = blockIdx.x * 8;

    __shared__ __align__(16) float2 sG[2][2][16][64];  // [buf][half][k][colpair]  32KB
    __shared__ __align__(16) float2 sA[2][2][8][16];   // dup pairs {a,a}           4KB
    __shared__ __align__(16) float2 red[8][64];        // cross-half reduction      4KB
    __shared__ float ws[2][8];                         // row-norm partials

    unsigned long long acc[8];
    #pragma unroll
    for (int m = 0; m < 8; m++) acc[m] = 0ull;

    const int kstart = h * 512;
    // A loader (per half, 64 threads cover 8 rows x 16 k, 2 contiguous k each)
    const int am  = x >> 3;          // 0..7  row
    const int ak2 = (x & 7) * 2;     // 0,2,..,14  k offset (float2 load)

    float4 xr[8];
    float2 ar;

    // ---- prologue: load + stage chunk 0 ----
    {
        const int k0 = kstart;
        #pragma unroll
        for (int j = 0; j < 8; j++) {
            const int u = x + 64 * j;            // 0..511 float4 units
            xr[j] = *(const float4*)&X[(k0 + (u >> 5)) * DIM + (u & 31) * 4];
        }
        ar = *(const float2*)&Am[(bm + am) * 1024 + k0 + ak2];
    }
    {
        #pragma unroll
        for (int j = 0; j < 8; j++) {
            const int u = x + 64 * j;
            *(float4*)&sG[0][h][u >> 5][(u & 31) * 2] = xr[j];
        }
        sA[0][h][am][ak2]     = make_float2(ar.x, ar.x);
        sA[0][h][am][ak2 + 1] = make_float2(ar.y, ar.y);
    }
    __syncthreads();

    // ---- main loop: 32 chunks of K=16, double buffered ----
    #pragma unroll 1
    for (int c = 0; c < 32; c++) {
        const int cur = c & 1;
        const int nxt = cur ^ 1;

        if (c < 31) {
            const int k0 = kstart + (c + 1) * 16;
            #pragma unroll
            for (int j = 0; j < 8; j++) {
                const int u = x + 64 * j;
                xr[j] = *(const float4*)&X[(k0 + (u >> 5)) * DIM + (u & 31) * 4];
            }
            ar = *(const float2*)&Am[(bm + am) * 1024 + k0 + ak2];
        }

        // compute on current buffer
        #pragma unroll
        for (int kk = 0; kk < 16; kk += 2) {
            const unsigned long long g0 =
                __double_as_longlong(*(const double*)&sG[cur][h][kk][x]);
            const unsigned long long g1 =
                __double_as_longlong(*(const double*)&sG[cur][h][kk + 1][x]);
            #pragma unroll
            for (int m = 0; m < 8; m++) {
                const double2 ad = *(const double2*)&sA[cur][h][m][kk];  // {a,a},{a',a'}
                ffma2(acc[m], __double_as_longlong(ad.x), g0);
                ffma2(acc[m], __double_as_longlong(ad.y), g1);
            }
        }

        if (c < 31) {
            #pragma unroll
            for (int j = 0; j < 8; j++) {
                const int u = x + 64 * j;
                *(float4*)&sG[nxt][h][u >> 5][(u & 31) * 2] = xr[j];
            }
            sA[nxt][h][am][ak2]     = make_float2(ar.x, ar.x);
            sA[nxt][h][am][ak2 + 1] = make_float2(ar.y, ar.y);
        }
        __syncthreads();
    }

    // ---- combine the two K halves ----
    if (h == 1) {
        #pragma unroll
        for (int m = 0; m < 8; m++) red[m][x] = unpack2(acc[m]);
    }
    __syncthreads();

    if (!EPI) {
        if (h == 0) {
            #pragma unroll
            for (int m = 0; m < 8; m++) {
                const float2 a2 = unpack2(acc[m]);
                const float2 b2 = red[m][x];
                *(float2*)&Y[(bm + m) * DIM + 2 * x] = make_float2(a2.x + b2.x, a2.y + b2.y);
            }
        }
        return;
    }

    // ---- fused epilogue: selu + row L2-normalize ----
    const float SELU_SCALE = 1.0507009873554804934f;
    const float SELU_ALPHA = 1.6732632423543772848f;

    float2 sv[8];
    if (h == 0) {
        #pragma unroll
        for (int m = 0; m < 8; m++) {
            const float2 a2 = unpack2(acc[m]);
            const float2 b2 = red[m][x];
            float vx = a2.x + b2.x, vy = a2.y + b2.y;
            sv[m].x = (vx > 0.f) ? SELU_SCALE * vx : SELU_SCALE * SELU_ALPHA * (expf(vx) - 1.f);
            sv[m].y = (vy > 0.f) ? SELU_SCALE * vy : SELU_SCALE * SELU_ALPHA * (expf(vy) - 1.f);
            float sq = sv[m].x * sv[m].x + sv[m].y * sv[m].y;
            #pragma unroll
            for (int o = 16; o; o >>= 1) sq += __shfl_xor_sync(0xFFFFFFFFu, sq, o);
            if ((x & 31) == 0) ws[x >> 5][m] = sq;   // warp 0 -> ws[0], warp 1 -> ws[1]
        }
    }
    __syncthreads();

    if (h == 0) {
        #pragma unroll
        for (int m = 0; m < 8; m++) {
            const float inv = rsqrtf(ws[0][m] + ws[1][m]);
            *(float2*)&Y[(bm + m) * DIM + 2 * x] =
                make_float2(sv[m].x * inv, sv[m].y * inv);
        }
    }
}

// ---------------------------------------------------------------------------
// Launch: gather -> ag = A@g -> out = norm(selu(D@ag))
// (attention/entmax path is analytically identity on g: scores constant
//  along L, entmax of a constant is uniform, sum(p)*g = g)
// ---------------------------------------------------------------------------
extern "C" void kernel_launch(void* const* d_in, const int* in_sizes, int n_in,
                              void* d_out, int out_size)
{
    const float* emb   = (const float*)d_in[0];  // [500000, 128]
    const void*  items = d_in[1];                // [1024, 200] int64/int32
    const float* Amat  = (const float*)d_in[2];  // [1024, 1024]
    const float* Dmat  = (const float*)d_in[3];  // [1024, 1024]
    float* out = (float*)d_out;                  // [1024, 128]

    float* g;  cudaGetSymbolAddress((void**)&g,  g_buf);
    float* ag; cudaGetSymbolAddress((void**)&ag, ag_buf);

    gather_sum_kernel<<<BATCH, DIM>>>(emb, items);

    dim3 gblk(64, 2);
    gemm_1024x128_kernel<false><<<BATCH / 8, gblk>>>(Amat, g, ag);   // ag = A@g
    gemm_1024x128_kernel<true ><<<BATCH / 8, gblk>>>(Dmat, ag, out); // out = norm(selu(D@ag))
}